// round 1
// baseline (speedup 1.0000x reference)
#include <cuda_runtime.h>
#include <math.h>

#define BB   8
#define VV   4
#define NPTS 16384
#define CP   256
#define BV   (BB*VV)            // 32
#define TM   64
#define NTILES (NPTS/TM)        // 256
#define NBLK  (BV*NTILES)       // 8192
#define EPS  1e-5f

// -------- scratch (static device memory; no runtime allocation) --------
__device__ float        g_center[BV*3];
__device__ float        g_diam[BV];
__device__ unsigned int g_gmaxu[BV*CP];
__device__ float        g_gcon[BV*CP];
__device__ float        g_local[(size_t)BV*NPTS*CP];      // 512 MB
__device__ float        g_poolpart[(size_t)NBLK*CP];      // 8 MB
__device__ float        g_denpart[NBLK];

// ordered-uint encoding so atomicMax works for signed floats
__device__ __forceinline__ unsigned fkey(float f) {
    unsigned u = __float_as_uint(f);
    return (u & 0x80000000u) ? ~u : (u | 0x80000000u);
}
__device__ __forceinline__ float fdec(unsigned k) {
    return __uint_as_float((k & 0x80000000u) ? (k ^ 0x80000000u) : ~k);
}

// ---------------- stage A: per-(b,v) center / diam ----------------
__global__ void stageA(const float* __restrict__ xyz, const float* __restrict__ masks) {
    int bv = blockIdx.x, b = bv >> 2, t = threadIdx.x;
    const float* xp = xyz + (size_t)b * 3 * NPTS;
    const float* mp = masks + (size_t)bv * NPTS;

    float s0 = 0.f, s1 = 0.f, s2 = 0.f, s3 = 0.f;
    float mn0 = 1e30f, mn1 = 1e30f, mn2 = 1e30f;
    float mx0 = -1e30f, mx1 = -1e30f, mx2 = -1e30f;
    for (int n = t; n < NPTS; n += 256) {
        float m = mp[n];
        float x = xp[n] * m, y = xp[NPTS + n] * m, z = xp[2 * NPTS + n] * m;
        s0 += x; s1 += y; s2 += z; s3 += m;
        mn0 = fminf(mn0, x); mx0 = fmaxf(mx0, x);
        mn1 = fminf(mn1, y); mx1 = fmaxf(mx1, y);
        mn2 = fminf(mn2, z); mx2 = fmaxf(mx2, z);
    }
    #pragma unroll
    for (int off = 16; off; off >>= 1) {
        s0 += __shfl_xor_sync(~0u, s0, off);
        s1 += __shfl_xor_sync(~0u, s1, off);
        s2 += __shfl_xor_sync(~0u, s2, off);
        s3 += __shfl_xor_sync(~0u, s3, off);
        mn0 = fminf(mn0, __shfl_xor_sync(~0u, mn0, off));
        mn1 = fminf(mn1, __shfl_xor_sync(~0u, mn1, off));
        mn2 = fminf(mn2, __shfl_xor_sync(~0u, mn2, off));
        mx0 = fmaxf(mx0, __shfl_xor_sync(~0u, mx0, off));
        mx1 = fmaxf(mx1, __shfl_xor_sync(~0u, mx1, off));
        mx2 = fmaxf(mx2, __shfl_xor_sync(~0u, mx2, off));
    }
    __shared__ float rb[8][10];
    int wid = t >> 5, lane = t & 31;
    if (lane == 0) {
        rb[wid][0] = s0; rb[wid][1] = s1; rb[wid][2] = s2; rb[wid][3] = s3;
        rb[wid][4] = mn0; rb[wid][5] = mn1; rb[wid][6] = mn2;
        rb[wid][7] = mx0; rb[wid][8] = mx1; rb[wid][9] = mx2;
    }
    __syncthreads();
    if (t == 0) {
        float S0 = 0, S1 = 0, S2 = 0, S3 = 0;
        float MN0 = 1e30f, MN1 = 1e30f, MN2 = 1e30f;
        float MX0 = -1e30f, MX1 = -1e30f, MX2 = -1e30f;
        for (int w = 0; w < 8; w++) {
            S0 += rb[w][0]; S1 += rb[w][1]; S2 += rb[w][2]; S3 += rb[w][3];
            MN0 = fminf(MN0, rb[w][4]); MN1 = fminf(MN1, rb[w][5]); MN2 = fminf(MN2, rb[w][6]);
            MX0 = fmaxf(MX0, rb[w][7]); MX1 = fmaxf(MX1, rb[w][8]); MX2 = fmaxf(MX2, rb[w][9]);
        }
        float valid = fmaxf(S3, 1.f);
        g_center[bv * 3 + 0] = S0 / valid;
        g_center[bv * 3 + 1] = S1 / valid;
        g_center[bv * 3 + 2] = S2 / valid;
        float d = fmaxf(fmaxf(MX0 - MN0, MX1 - MN1), MX2 - MN2);
        g_diam[bv] = (d == 0.f) ? 1.f : d;
    }
    g_gmaxu[bv * CP + t] = 0u;   // -inf key
}

// per-row LayerNorm (in place) on H[TM][CP]; warp w handles rows 8w..8w+7
__device__ __forceinline__ void ln_rows(float* H, const float* __restrict__ g,
                                        const float* __restrict__ be, bool do_relu) {
    int wid = threadIdx.x >> 5, lane = threadIdx.x & 31;
    #pragma unroll 1
    for (int r = 0; r < 8; r++) {
        int m = wid * 8 + r;
        float* row = H + m * CP;
        float v[8]; float s = 0.f, s2 = 0.f;
        #pragma unroll
        for (int i = 0; i < 8; i++) {
            v[i] = row[lane + 32 * i];
            s += v[i]; s2 += v[i] * v[i];
        }
        #pragma unroll
        for (int off = 16; off; off >>= 1) {
            s  += __shfl_xor_sync(~0u, s, off);
            s2 += __shfl_xor_sync(~0u, s2, off);
        }
        float mean = s * (1.f / CP);
        float var  = s2 * (1.f / CP) - mean * mean;
        float inv  = rsqrtf(var + EPS);
        #pragma unroll
        for (int i = 0; i < 8; i++) {
            int c = lane + 32 * i;
            float o = (v[i] - mean) * inv * g[c] + be[c];
            if (do_relu) o = fmaxf(o, 0.f);
            row[c] = o;
        }
    }
}

// ---------------- stage B: point MLP 1, write local + global max ----------------
__global__ __launch_bounds__(256) void stageB(
    const float* __restrict__ xyz, const float* __restrict__ W1, const float* __restrict__ b1,
    const float* __restrict__ g1, const float* __restrict__ be1,
    const float* __restrict__ W2, const float* __restrict__ b2,
    const float* __restrict__ g2, const float* __restrict__ be2) {
    extern __shared__ float sm[];
    float* H  = sm;                 // [TM][CP]
    float* sx = sm + TM * CP;       // [TM]
    float* sy = sx + TM;
    float* sz = sy + TM;

    int bv = blockIdx.x / NTILES, tile = blockIdx.x % NTILES;
    int b = bv >> 2, n0 = tile * TM, t = threadIdx.x;

    float cx = g_center[bv * 3 + 0], cy = g_center[bv * 3 + 1], cz = g_center[bv * 3 + 2];
    float dinv = 1.f / g_diam[bv];
    if (t < TM) {
        const float* xp = xyz + (size_t)b * 3 * NPTS;
        int n = n0 + t;
        sx[t] = (xp[n] - cx) * dinv;
        sy[t] = (xp[NPTS + n] - cy) * dinv;
        sz[t] = (xp[2 * NPTS + n] - cz) * dinv;
    }
    __syncthreads();

    // h0 = norm_xyz @ W1 + b1
    for (int idx = t; idx < TM * CP; idx += 256) {
        int m = idx >> 8, c = idx & (CP - 1);
        H[idx] = sx[m] * W1[c] + sy[m] * W1[CP + c] + sz[m] * W1[2 * CP + c] + b1[c];
    }
    __syncthreads();
    ln_rows(H, g1, be1, true);
    __syncthreads();

    // GEMM: out[m][t] = sum_k H[m][k] * W2[k][t]
    float acc[TM];
    #pragma unroll
    for (int m = 0; m < TM; m++) acc[m] = 0.f;
    #pragma unroll 1
    for (int k = 0; k < CP; k += 4) {
        float w0 = W2[(k + 0) * CP + t];
        float w1 = W2[(k + 1) * CP + t];
        float w2 = W2[(k + 2) * CP + t];
        float w3 = W2[(k + 3) * CP + t];
        #pragma unroll
        for (int m = 0; m < TM; m++) {
            float4 h = *(const float4*)&H[m * CP + k];
            acc[m] += h.x * w0 + h.y * w1 + h.z * w2 + h.w * w3;
        }
    }
    __syncthreads();
    float bb = b2[t];
    #pragma unroll
    for (int m = 0; m < TM; m++) H[m * CP + t] = acc[m] + bb;
    __syncthreads();
    ln_rows(H, g2, be2, false);
    __syncthreads();

    // store local tile + column max -> global max
    float* Lg = g_local + ((size_t)(bv * NPTS + n0)) * CP;
    float gm = -1e30f;
    #pragma unroll 4
    for (int m = 0; m < TM; m++) {
        float vl = H[m * CP + t];
        gm = fmaxf(gm, vl);
        Lg[(size_t)m * CP + t] = vl;
    }
    atomicMax(&g_gmaxu[bv * CP + t], fkey(gm));
}

// ---------------- stage G: gcontrib = b3 + global_xyz @ W3[256:512] ----------------
__global__ void stageG(const float* __restrict__ W3, const float* __restrict__ b3) {
    __shared__ float gsm[CP];
    int bv = blockIdx.x, t = threadIdx.x;
    gsm[t] = fdec(g_gmaxu[bv * CP + t]);
    __syncthreads();
    float a = b3[t];
    #pragma unroll 4
    for (int j = 0; j < CP; j++) a += gsm[j] * W3[(CP + j) * CP + t];
    g_gcon[bv * CP + t] = a;
}

// ---------------- stage C: MLP2 + weights + pooling partials ----------------
__global__ __launch_bounds__(256) void stageC(
    const float* __restrict__ feats, const float* __restrict__ masks,
    const float* __restrict__ W3, const float* __restrict__ g3,
    const float* __restrict__ be3, const float* __restrict__ W4) {
    extern __shared__ float sm[];
    float* L     = sm;                  // [TM][CP]
    float* wRow  = sm + TM * CP;        // [TM]
    float* mwRow = wRow + TM;           // [TM]

    int bv = blockIdx.x / NTILES, tile = blockIdx.x % NTILES;
    int b = bv >> 2, n0 = tile * TM, t = threadIdx.x;

    const float* Lg = g_local + ((size_t)(bv * NPTS + n0)) * CP;
    for (int idx = t; idx < TM * CP; idx += 256) L[idx] = Lg[idx];
    __syncthreads();

    float acc[TM];
    #pragma unroll
    for (int m = 0; m < TM; m++) acc[m] = 0.f;
    #pragma unroll 1
    for (int k = 0; k < CP; k += 4) {
        float w0 = W3[(k + 0) * CP + t];
        float w1 = W3[(k + 1) * CP + t];
        float w2 = W3[(k + 2) * CP + t];
        float w3 = W3[(k + 3) * CP + t];
        #pragma unroll
        for (int m = 0; m < TM; m++) {
            float4 h = *(const float4*)&L[m * CP + k];
            acc[m] += h.x * w0 + h.y * w1 + h.z * w2 + h.w * w3;
        }
    }
    __syncthreads();
    float gc = g_gcon[bv * CP + t];
    #pragma unroll
    for (int m = 0; m < TM; m++) L[m * CP + t] = acc[m] + gc;
    __syncthreads();
    ln_rows(L, g3, be3, true);
    __syncthreads();

    // weights: sigmoid(h2 @ W4) * 2, one warp per 8 rows
    {
        int wid = t >> 5, lane = t & 31;
        #pragma unroll 1
        for (int r = 0; r < 8; r++) {
            int m = wid * 8 + r;
            float s = 0.f;
            #pragma unroll
            for (int i = 0; i < 8; i++) {
                int c = lane + 32 * i;
                s += L[m * CP + c] * W4[c];
            }
            #pragma unroll
            for (int off = 16; off; off >>= 1) s += __shfl_xor_sync(~0u, s, off);
            if (lane == 0) wRow[m] = 2.f / (1.f + expf(-s));
        }
    }
    __syncthreads();
    if (t < TM) mwRow[t] = wRow[t] * masks[(size_t)bv * NPTS + n0 + t];
    __syncthreads();

    // pooled partial for this tile: thread t owns channel t
    const float* fp = feats + (size_t)b * CP * NPTS + (size_t)t * NPTS + n0;
    float p = 0.f;
    #pragma unroll 8
    for (int m = 0; m < TM; m++) p += fp[m] * mwRow[m];
    g_poolpart[((size_t)blockIdx.x) * CP + t] = p;
    if (t == 0) {
        float d = 0.f;
        for (int m = 0; m < TM; m++) d += mwRow[m];
        g_denpart[blockIdx.x] = d;
    }
}

// ---------------- stage D: final reduce ----------------
__global__ void stageD(float* __restrict__ out) {
    int bv = blockIdx.x, t = threadIdx.x;
    __shared__ float dsum_s;
    float p = 0.f;
    for (int tl = 0; tl < NTILES; tl++)
        p += g_poolpart[((size_t)(bv * NTILES + tl)) * CP + t];
    if (t == 0) {
        float d = 0.f;
        for (int tl = 0; tl < NTILES; tl++) d += g_denpart[bv * NTILES + tl];
        dsum_s = fmaxf(d, 1e-8f);
    }
    __syncthreads();
    out[bv * CP + t] = p / dsum_s + fdec(g_gmaxu[bv * CP + t]);
}

extern "C" void kernel_launch(void* const* d_in, const int* in_sizes, int n_in,
                              void* d_out, int out_size) {
    const float* xyz   = (const float*)d_in[0];
    const float* feats = (const float*)d_in[1];
    const float* masks = (const float*)d_in[2];
    const float* W1  = (const float*)d_in[3];
    const float* b1  = (const float*)d_in[4];
    const float* g1  = (const float*)d_in[5];
    const float* be1 = (const float*)d_in[6];
    const float* W2  = (const float*)d_in[7];
    const float* b2  = (const float*)d_in[8];
    const float* g2  = (const float*)d_in[9];
    const float* be2 = (const float*)d_in[10];
    const float* W3  = (const float*)d_in[11];
    const float* b3  = (const float*)d_in[12];
    const float* g3  = (const float*)d_in[13];
    const float* be3 = (const float*)d_in[14];
    const float* W4  = (const float*)d_in[15];

    size_t smB = (TM * CP + 3 * TM + 16) * sizeof(float);   // ~66.3 KB
    size_t smC = (TM * CP + 2 * TM + 16) * sizeof(float);
    cudaFuncSetAttribute(stageB, cudaFuncAttributeMaxDynamicSharedMemorySize, (int)smB);
    cudaFuncSetAttribute(stageC, cudaFuncAttributeMaxDynamicSharedMemorySize, (int)smC);

    stageA<<<BV, 256>>>(xyz, masks);
    stageB<<<NBLK, 256, smB>>>(xyz, W1, b1, g1, be1, W2, b2, g2, be2);
    stageG<<<BV, CP>>>(W3, b3);
    stageC<<<NBLK, 256, smC>>>(feats, masks, W3, g3, be3, W4);
    stageD<<<BV, CP>>>((float*)d_out);
}

// round 3
// speedup vs baseline: 2.5793x; 2.5793x over previous
#include <cuda_runtime.h>
#include <cuda_bf16.h>
#include <cstdint>
#include <math.h>

#define BB 8
#define VV 4
#define NPTS 16384
#define CP 256
#define BV 32
#define TM 128
#define NTILES 128
#define NBLK (BV*NTILES)      // 4096
#define EPS 1e-5f

// ---------------- device scratch ----------------
__device__ float    g_center[BV*3];
__device__ float    g_diam[BV];
__device__ unsigned g_gmaxu[BV*CP];
__device__ float    g_gcon[BV*CP];
// prepped weights: per matrix, [ck][n][physword] u32 (bf16 pairs along k), 4*8192 u32
__device__ __align__(16) unsigned gW2h[32768], gW2l[32768];
__device__ __align__(16) unsigned gW3h[32768], gW3l[32768];
// local features, stored as the exact A-operand smem image per tile: [tile][16384 u32]
__device__ __align__(16) unsigned g_localH[(size_t)NBLK*16384];
__device__ __align__(16) unsigned g_localL[(size_t)NBLK*16384];
__device__ float    g_poolpart[(size_t)NBLK*CP];
__device__ float    g_denpart[NBLK];

// ---------------- helpers ----------------
__device__ __forceinline__ unsigned fkey(float f) {
    unsigned u = __float_as_uint(f);
    return (u & 0x80000000u) ? ~u : (u | 0x80000000u);
}
__device__ __forceinline__ float fdec(unsigned k) {
    return __uint_as_float((k & 0x80000000u) ? (k ^ 0x80000000u) : ~k);
}
__device__ __forceinline__ unsigned short bfbits(__nv_bfloat16 h) {
    union { __nv_bfloat16 b; unsigned short u; } x; x.b = h; return x.u;
}
__device__ __forceinline__ void split_bf(float y, unsigned short& h, unsigned short& l) {
    __nv_bfloat16 hb = __float2bfloat16(y);
    float hr = __bfloat162float(hb);
    __nv_bfloat16 lb = __float2bfloat16(y - hr);
    h = bfbits(hb); l = bfbits(lb);
}
// A smem swizzle: word w (0..127) within row m -> conflict-free for frag reads & staged writes
__device__ __forceinline__ unsigned physA(unsigned w, unsigned row) {
    return (w ^ (((row) & 7u) << 2) ^ (w >> 5)) & 127u;
}
__device__ __forceinline__ void mma16816(float* d, const unsigned* a, const unsigned* b) {
    asm volatile(
        "mma.sync.aligned.m16n8k16.row.col.f32.bf16.bf16.f32 "
        "{%0,%1,%2,%3}, {%4,%5,%6,%7}, {%8,%9}, {%0,%1,%2,%3};"
        : "+f"(d[0]), "+f"(d[1]), "+f"(d[2]), "+f"(d[3])
        : "r"(a[0]), "r"(a[1]), "r"(a[2]), "r"(a[3]), "r"(b[0]), "r"(b[1]));
}

// dynamic smem: AH 16384 u32 | AL 16384 | BH 8192 | BL 8192  = 192 KB
#define DSMEM_U32 (16384*2 + 8192*2)
#define DSMEM_BYTES (DSMEM_U32*4)

// ---------------- prep: split + transpose + swizzle W2/W3 ----------------
__global__ void prepW(const float* __restrict__ W2, const float* __restrict__ W3) {
    int idx = blockIdx.x * 256 + threadIdx.x;     // 0..65535
    int mat = idx >> 15;
    int e = idx & 32767;
    int n = e & 255, kp = e >> 8;                 // kp 0..127
    int ck = kp >> 5, wv = kp & 31;
    int k = ck * 64 + wv * 2;
    const float* W = mat ? W3 : W2;
    float v0 = W[k * CP + n], v1 = W[(k + 1) * CP + n];
    unsigned short h0, l0, h1, l1;
    split_bf(v0, h0, l0); split_bf(v1, h1, l1);
    unsigned hw = (unsigned)h0 | ((unsigned)h1 << 16);
    unsigned lw = (unsigned)l0 | ((unsigned)l1 << 16);
    int dst = ck * 8192 + n * 32 + ((wv + 4 * n) & 31);
    if (mat) { gW3h[dst] = hw; gW3l[dst] = lw; }
    else     { gW2h[dst] = hw; gW2l[dst] = lw; }
}

// ---------------- stage A: per-(b,v) center / diam ----------------
__global__ void stageA(const float* __restrict__ xyz, const float* __restrict__ masks) {
    int bv = blockIdx.x, b = bv >> 2, t = threadIdx.x;
    const float* xp = xyz + (size_t)b * 3 * NPTS;
    const float* mp = masks + (size_t)bv * NPTS;
    float s0 = 0.f, s1 = 0.f, s2 = 0.f, s3 = 0.f;
    float mn0 = 1e30f, mn1 = 1e30f, mn2 = 1e30f;
    float mx0 = -1e30f, mx1 = -1e30f, mx2 = -1e30f;
    for (int n = t; n < NPTS; n += 256) {
        float m = mp[n];
        float x = xp[n] * m, y = xp[NPTS + n] * m, z = xp[2 * NPTS + n] * m;
        s0 += x; s1 += y; s2 += z; s3 += m;
        mn0 = fminf(mn0, x); mx0 = fmaxf(mx0, x);
        mn1 = fminf(mn1, y); mx1 = fmaxf(mx1, y);
        mn2 = fminf(mn2, z); mx2 = fmaxf(mx2, z);
    }
    #pragma unroll
    for (int off = 16; off; off >>= 1) {
        s0 += __shfl_xor_sync(~0u, s0, off);
        s1 += __shfl_xor_sync(~0u, s1, off);
        s2 += __shfl_xor_sync(~0u, s2, off);
        s3 += __shfl_xor_sync(~0u, s3, off);
        mn0 = fminf(mn0, __shfl_xor_sync(~0u, mn0, off));
        mn1 = fminf(mn1, __shfl_xor_sync(~0u, mn1, off));
        mn2 = fminf(mn2, __shfl_xor_sync(~0u, mn2, off));
        mx0 = fmaxf(mx0, __shfl_xor_sync(~0u, mx0, off));
        mx1 = fmaxf(mx1, __shfl_xor_sync(~0u, mx1, off));
        mx2 = fmaxf(mx2, __shfl_xor_sync(~0u, mx2, off));
    }
    __shared__ float rb[8][10];
    int wid = t >> 5, lane = t & 31;
    if (lane == 0) {
        rb[wid][0] = s0; rb[wid][1] = s1; rb[wid][2] = s2; rb[wid][3] = s3;
        rb[wid][4] = mn0; rb[wid][5] = mn1; rb[wid][6] = mn2;
        rb[wid][7] = mx0; rb[wid][8] = mx1; rb[wid][9] = mx2;
    }
    __syncthreads();
    if (t == 0) {
        float S0 = 0, S1 = 0, S2 = 0, S3 = 0;
        float MN0 = 1e30f, MN1 = 1e30f, MN2 = 1e30f;
        float MX0 = -1e30f, MX1 = -1e30f, MX2 = -1e30f;
        for (int w = 0; w < 8; w++) {
            S0 += rb[w][0]; S1 += rb[w][1]; S2 += rb[w][2]; S3 += rb[w][3];
            MN0 = fminf(MN0, rb[w][4]); MN1 = fminf(MN1, rb[w][5]); MN2 = fminf(MN2, rb[w][6]);
            MX0 = fmaxf(MX0, rb[w][7]); MX1 = fmaxf(MX1, rb[w][8]); MX2 = fmaxf(MX2, rb[w][9]);
        }
        float valid = fmaxf(S3, 1.f);
        g_center[bv * 3 + 0] = S0 / valid;
        g_center[bv * 3 + 1] = S1 / valid;
        g_center[bv * 3 + 2] = S2 / valid;
        float d = fmaxf(fmaxf(MX0 - MN0, MX1 - MN1), MX2 - MN2);
        g_diam[bv] = (d == 0.f) ? 1.f : d;
    }
    g_gmaxu[bv * CP + t] = 0u;
}

// ---------------- shared mainloop (A,B in smem -> acc regs) ----------------
__device__ __forceinline__ void gemm_mainloop(
    const unsigned* AH, const unsigned* AL, unsigned* BH, unsigned* BL,
    const unsigned* gWh, const unsigned* gWl,
    float* acc, int t, int g, int r4, int m0w, int n0w)
{
    #pragma unroll 1
    for (int ck = 0; ck < 4; ck++) {
        __syncthreads();
        {
            const uint4* sh = (const uint4*)(gWh + ck * 8192);
            const uint4* sl = (const uint4*)(gWl + ck * 8192);
            uint4* dh = (uint4*)BH; uint4* dl = (uint4*)BL;
            #pragma unroll
            for (int i = 0; i < 4; i++) { dh[t + i * 512] = sh[t + i * 512]; dl[t + i * 512] = sl[t + i * 512]; }
        }
        __syncthreads();
        #pragma unroll
        for (int kk = 0; kk < 4; kk++) {
            unsigned ah[2][4], al[2][4];
            unsigned w0 = (unsigned)(ck * 32 + kk * 8 + r4);
            #pragma unroll
            for (int mi = 0; mi < 2; mi++) {
                unsigned row = (unsigned)(m0w + mi * 16 + g);
                unsigned base = row * 128u;
                unsigned p0 = physA(w0, row), p2 = physA(w0 + 4, row);
                ah[mi][0] = AH[base + p0];        ah[mi][1] = AH[base + 1024 + p0];
                ah[mi][2] = AH[base + p2];        ah[mi][3] = AH[base + 1024 + p2];
                al[mi][0] = AL[base + p0];        al[mi][1] = AL[base + 1024 + p0];
                al[mi][2] = AL[base + p2];        al[mi][3] = AL[base + 1024 + p2];
            }
            #pragma unroll
            for (int ni = 0; ni < 8; ni++) {
                unsigned n = (unsigned)(n0w + ni * 8 + g);
                unsigned bw = (unsigned)(kk * 8 + r4);
                unsigned pb0 = (bw + 4u * n) & 31u, pb1 = (bw + 4u + 4u * n) & 31u;
                unsigned bh[2] = { BH[n * 32 + pb0], BH[n * 32 + pb1] };
                unsigned bl[2] = { BL[n * 32 + pb0], BL[n * 32 + pb1] };
                #pragma unroll
                for (int mi = 0; mi < 2; mi++) {
                    float* d = acc + mi * 32 + ni * 4;
                    mma16816(d, ah[mi], bh);
                    mma16816(d, al[mi], bh);
                    mma16816(d, ah[mi], bl);
                }
            }
        }
    }
}

// ---------------- stage B ----------------
__global__ __launch_bounds__(512, 1) void stageB(
    const float* __restrict__ xyz,
    const float* __restrict__ W1, const float* __restrict__ b1,
    const float* __restrict__ g1v, const float* __restrict__ be1,
    const float* __restrict__ b2, const float* __restrict__ g2v,
    const float* __restrict__ be2)
{
    extern __shared__ unsigned smu[];
    unsigned* AH = smu;
    unsigned* AL = smu + 16384;
    unsigned* BH = smu + 32768;
    unsigned* BL = smu + 40960;
    __shared__ float W1s[3 * CP], b1s[CP], g1s[CP], be1s[CP], b2s[CP], g2s[CP], be2s[CP];
    __shared__ float rr_s[TM][4], rr_s2[TM][4], mean_s[TM], inv_s[TM];

    int t = threadIdx.x, lane = t & 31, wid = t >> 5;
    int g = lane >> 2, r4 = lane & 3;
    int bv = blockIdx.x >> 7, tile = blockIdx.x & 127;
    int b = bv >> 2, n0 = tile * TM;

    for (int i = t; i < CP; i += 512) {
        W1s[i] = W1[i]; W1s[CP + i] = W1[CP + i]; W1s[2 * CP + i] = W1[2 * CP + i];
        b1s[i] = b1[i]; g1s[i] = g1v[i]; be1s[i] = be1[i];
        b2s[i] = b2[i]; g2s[i] = g2v[i]; be2s[i] = be2[i];
    }

    // ---- pass 1: h0 = LN(relu? no: relu(LN(xyzn@W1+b1))) -> A operand in smem ----
    int m = t >> 2, q = t & 3;
    float cx = g_center[bv * 3 + 0], cy = g_center[bv * 3 + 1], cz = g_center[bv * 3 + 2];
    float dinv = 1.f / g_diam[bv];
    const float* xp = xyz + (size_t)b * 3 * NPTS;
    float sx = (xp[n0 + m] - cx) * dinv;
    float sy = (xp[NPTS + n0 + m] - cy) * dinv;
    float sz = (xp[2 * NPTS + n0 + m] - cz) * dinv;
    __syncthreads();

    {
        float v[64]; float s = 0.f, s2 = 0.f;
        #pragma unroll
        for (int i = 0; i < 64; i++) {
            int c = q * 64 + i;
            v[i] = fmaf(sx, W1s[c], fmaf(sy, W1s[CP + c], fmaf(sz, W1s[2 * CP + c], b1s[c])));
            s += v[i]; s2 += v[i] * v[i];
        }
        s  += __shfl_xor_sync(~0u, s, 1);  s  += __shfl_xor_sync(~0u, s, 2);
        s2 += __shfl_xor_sync(~0u, s2, 1); s2 += __shfl_xor_sync(~0u, s2, 2);
        float mu = s * (1.f / CP);
        float var = s2 * (1.f / CP) - mu * mu;
        float iv = rsqrtf(var + EPS);
        #pragma unroll
        for (int i = 0; i < 64; i += 2) {
            int c = q * 64 + i;
            float y0 = fmaxf((v[i] - mu) * iv * g1s[c] + be1s[c], 0.f);
            float y1 = fmaxf((v[i + 1] - mu) * iv * g1s[c + 1] + be1s[c + 1], 0.f);
            unsigned short h0, l0, h1, l1;
            split_bf(y0, h0, l0); split_bf(y1, h1, l1);
            unsigned w = (unsigned)(c >> 1);
            unsigned idx = (unsigned)m * 128u + physA(w, (unsigned)m);
            AH[idx] = (unsigned)h0 | ((unsigned)h1 << 16);
            AL[idx] = (unsigned)l0 | ((unsigned)l1 << 16);
        }
    }

    // ---- mainloop ----
    int m0w = (wid & 3) * 32, n0w = (wid >> 2) * 64;
    float acc[64];
    #pragma unroll
    for (int i = 0; i < 64; i++) acc[i] = 0.f;
    gemm_mainloop(AH, AL, BH, BL, gW2h, gW2l, acc, t, g, r4, m0w, n0w);

    // ---- epilogue: +b2, LN2, col-max, split -> staged smem -> g_local ----
    int wn = wid >> 2;
    #pragma unroll
    for (int mh = 0; mh < 4; mh++) {
        int mi = mh >> 1, h = mh & 1;
        int row = m0w + mi * 16 + g + 8 * h;
        float s = 0.f, s2 = 0.f;
        #pragma unroll
        for (int ni = 0; ni < 8; ni++) {
            #pragma unroll
            for (int r01 = 0; r01 < 2; r01++) {
                int c = n0w + ni * 8 + r4 * 2 + r01;
                float vv = acc[mi * 32 + ni * 4 + 2 * h + r01] + b2s[c];
                s += vv; s2 += vv * vv;
            }
        }
        s  += __shfl_xor_sync(~0u, s, 1);  s  += __shfl_xor_sync(~0u, s, 2);
        s2 += __shfl_xor_sync(~0u, s2, 1); s2 += __shfl_xor_sync(~0u, s2, 2);
        if (r4 == 0) { rr_s[row][wn] = s; rr_s2[row][wn] = s2; }
    }
    __syncthreads();
    if (t < TM) {
        float S = rr_s[t][0] + rr_s[t][1] + rr_s[t][2] + rr_s[t][3];
        float S2 = rr_s2[t][0] + rr_s2[t][1] + rr_s2[t][2] + rr_s2[t][3];
        float mu = S * (1.f / CP);
        float var = S2 * (1.f / CP) - mu * mu;
        mean_s[t] = mu; inv_s[t] = rsqrtf(var + EPS);
    }
    __syncthreads();

    float cmax[16];
    #pragma unroll
    for (int j = 0; j < 16; j++) cmax[j] = -1e30f;
    #pragma unroll
    for (int mh = 0; mh < 4; mh++) {
        int mi = mh >> 1, h = mh & 1;
        int row = m0w + mi * 16 + g + 8 * h;
        float mu = mean_s[row], iv = inv_s[row];
        #pragma unroll
        for (int ni = 0; ni < 8; ni++) {
            int c0 = n0w + ni * 8 + r4 * 2;
            float y0 = (acc[mi * 32 + ni * 4 + 2 * h] + b2s[c0] - mu) * iv * g2s[c0] + be2s[c0];
            float y1 = (acc[mi * 32 + ni * 4 + 2 * h + 1] + b2s[c0 + 1] - mu) * iv * g2s[c0 + 1] + be2s[c0 + 1];
            cmax[ni * 2]     = fmaxf(cmax[ni * 2], y0);
            cmax[ni * 2 + 1] = fmaxf(cmax[ni * 2 + 1], y1);
            unsigned short h0, l0, h1, l1;
            split_bf(y0, h0, l0); split_bf(y1, h1, l1);
            unsigned w = (unsigned)((n0w >> 1) + ni * 4 + r4);
            unsigned idx = (unsigned)row * 128u + physA(w, (unsigned)row);
            AH[idx] = (unsigned)h0 | ((unsigned)h1 << 16);
            AL[idx] = (unsigned)l0 | ((unsigned)l1 << 16);
        }
    }
    // col-max reduce over row-groups (lanes sharing r4)
    #pragma unroll
    for (int j = 0; j < 16; j++) {
        cmax[j] = fmaxf(cmax[j], __shfl_xor_sync(~0u, cmax[j], 4));
        cmax[j] = fmaxf(cmax[j], __shfl_xor_sync(~0u, cmax[j], 8));
        cmax[j] = fmaxf(cmax[j], __shfl_xor_sync(~0u, cmax[j], 16));
    }
    if (lane < 4) {
        #pragma unroll
        for (int ni = 0; ni < 8; ni++) {
            int c0 = n0w + ni * 8 + lane * 2;
            atomicMax(&g_gmaxu[bv * CP + c0], fkey(cmax[ni * 2]));
            atomicMax(&g_gmaxu[bv * CP + c0 + 1], fkey(cmax[ni * 2 + 1]));
        }
    }
    __syncthreads();
    {
        size_t gb = (size_t)blockIdx.x * 16384;
        uint4* dh = (uint4*)(g_localH + gb);
        uint4* dl = (uint4*)(g_localL + gb);
        const uint4* sh = (const uint4*)AH;
        const uint4* sl = (const uint4*)AL;
        #pragma unroll
        for (int i = 0; i < 8; i++) { dh[t + i * 512] = sh[t + i * 512]; dl[t + i * 512] = sl[t + i * 512]; }
    }
}

// ---------------- stage G: gcon = b3 + global @ W3[256:512] ----------------
__global__ void stageG(const float* __restrict__ W3, const float* __restrict__ b3) {
    __shared__ float gsm[CP];
    int bv = blockIdx.x, t = threadIdx.x;
    gsm[t] = fdec(g_gmaxu[bv * CP + t]);
    __syncthreads();
    float a = b3[t];
    #pragma unroll 4
    for (int j = 0; j < CP; j++) a = fmaf(gsm[j], W3[(CP + j) * CP + t], a);
    g_gcon[bv * CP + t] = a;
}

// ---------------- stage C ----------------
__global__ __launch_bounds__(512, 1) void stageC(
    const float* __restrict__ feats, const float* __restrict__ masks,
    const float* __restrict__ g3v, const float* __restrict__ be3,
    const float* __restrict__ W4)
{
    extern __shared__ unsigned smu[];
    unsigned* AH = smu;
    unsigned* AL = smu + 16384;
    unsigned* BH = smu + 32768;
    unsigned* BL = smu + 40960;
    __shared__ float gcs[CP], g3s[CP], be3s[CP], W4s[CP];
    __shared__ float rr_s[TM][4], rr_s2[TM][4], mean_s[TM], inv_s[TM];
    __shared__ __align__(16) float mw_s[TM];

    int t = threadIdx.x, lane = t & 31, wid = t >> 5;
    int g = lane >> 2, r4 = lane & 3;
    int bv = blockIdx.x >> 7, tile = blockIdx.x & 127;
    int b = bv >> 2, n0 = tile * TM;

    for (int i = t; i < CP; i += 512) {
        gcs[i] = g_gcon[bv * CP + i];
        g3s[i] = g3v[i]; be3s[i] = be3[i]; W4s[i] = W4[i];
    }
    // A operand: linear copy of stage-B image
    {
        size_t gb = (size_t)blockIdx.x * 16384;
        const uint4* sh = (const uint4*)(g_localH + gb);
        const uint4* sl = (const uint4*)(g_localL + gb);
        uint4* dh = (uint4*)AH; uint4* dl = (uint4*)AL;
        #pragma unroll
        for (int i = 0; i < 8; i++) { dh[t + i * 512] = sh[t + i * 512]; dl[t + i * 512] = sl[t + i * 512]; }
    }

    int m0w = (wid & 3) * 32, n0w = (wid >> 2) * 64;
    float acc[64];
    #pragma unroll
    for (int i = 0; i < 64; i++) acc[i] = 0.f;
    gemm_mainloop(AH, AL, BH, BL, gW3h, gW3l, acc, t, g, r4, m0w, n0w);

    // ---- epilogue: +gcon, LN3, relu, dot W4, sigmoid -> mw ----
    int wn = wid >> 2;
    #pragma unroll
    for (int mh = 0; mh < 4; mh++) {
        int mi = mh >> 1, h = mh & 1;
        int row = m0w + mi * 16 + g + 8 * h;
        float s = 0.f, s2 = 0.f;
        #pragma unroll
        for (int ni = 0; ni < 8; ni++) {
            #pragma unroll
            for (int r01 = 0; r01 < 2; r01++) {
                int c = n0w + ni * 8 + r4 * 2 + r01;
                float vv = acc[mi * 32 + ni * 4 + 2 * h + r01] + gcs[c];
                s += vv; s2 += vv * vv;
            }
        }
        s  += __shfl_xor_sync(~0u, s, 1);  s  += __shfl_xor_sync(~0u, s, 2);
        s2 += __shfl_xor_sync(~0u, s2, 1); s2 += __shfl_xor_sync(~0u, s2, 2);
        if (r4 == 0) { rr_s[row][wn] = s; rr_s2[row][wn] = s2; }
    }
    __syncthreads();
    if (t < TM) {
        float S = rr_s[t][0] + rr_s[t][1] + rr_s[t][2] + rr_s[t][3];
        float S2 = rr_s2[t][0] + rr_s2[t][1] + rr_s2[t][2] + rr_s2[t][3];
        float mu = S * (1.f / CP);
        float var = S2 * (1.f / CP) - mu * mu;
        mean_s[t] = mu; inv_s[t] = rsqrtf(var + EPS);
    }
    __syncthreads();
    #pragma unroll
    for (int mh = 0; mh < 4; mh++) {
        int mi = mh >> 1, h = mh & 1;
        int row = m0w + mi * 16 + g + 8 * h;
        float mu = mean_s[row], iv = inv_s[row];
        float dp = 0.f;
        #pragma unroll
        for (int ni = 0; ni < 8; ni++) {
            #pragma unroll
            for (int r01 = 0; r01 < 2; r01++) {
                int c = n0w + ni * 8 + r4 * 2 + r01;
                float y = fmaxf((acc[mi * 32 + ni * 4 + 2 * h + r01] + gcs[c] - mu) * iv * g3s[c] + be3s[c], 0.f);
                dp = fmaf(y, W4s[c], dp);
            }
        }
        dp += __shfl_xor_sync(~0u, dp, 1); dp += __shfl_xor_sync(~0u, dp, 2);
        if (r4 == 0) rr_s[row][wn] = dp;
    }
    __syncthreads();
    if (t < TM) {
        float dpv = rr_s[t][0] + rr_s[t][1] + rr_s[t][2] + rr_s[t][3];
        float w = 2.f / (1.f + expf(-dpv));
        mw_s[t] = w * masks[(size_t)bv * NPTS + n0 + t];
    }
    __syncthreads();

    // ---- pooling: warp per 16 channels ----
    const float* fb = feats + (size_t)b * CP * NPTS;
    float4 m4 = ((const float4*)mw_s)[lane];
    #pragma unroll 1
    for (int ci = 0; ci < 16; ci++) {
        int c = wid * 16 + ci;
        float4 f = *(const float4*)(fb + (size_t)c * NPTS + n0 + lane * 4);
        float p = f.x * m4.x + f.y * m4.y + f.z * m4.z + f.w * m4.w;
        #pragma unroll
        for (int off = 16; off; off >>= 1) p += __shfl_xor_sync(~0u, p, off);
        if (lane == 0) g_poolpart[(size_t)blockIdx.x * CP + c] = p;
    }
    if (wid == 0) {
        float d = mw_s[lane] + mw_s[lane + 32] + mw_s[lane + 64] + mw_s[lane + 96];
        #pragma unroll
        for (int off = 16; off; off >>= 1) d += __shfl_xor_sync(~0u, d, off);
        if (lane == 0) g_denpart[blockIdx.x] = d;
    }
}

// ---------------- stage D: final reduce ----------------
__global__ void stageD(float* __restrict__ out) {
    int bv = blockIdx.x, t = threadIdx.x;
    __shared__ float dsum_s;
    float p = 0.f;
    for (int tl = 0; tl < NTILES; tl++)
        p += g_poolpart[((size_t)(bv * NTILES + tl)) * CP + t];
    if (t == 0) {
        float d = 0.f;
        for (int tl = 0; tl < NTILES; tl++) d += g_denpart[bv * NTILES + tl];
        dsum_s = fmaxf(d, 1e-8f);
    }
    __syncthreads();
    out[bv * CP + t] = p / dsum_s + fdec(g_gmaxu[bv * CP + t]);
}

extern "C" void kernel_launch(void* const* d_in, const int* in_sizes, int n_in,
                              void* d_out, int out_size) {
    const float* xyz   = (const float*)d_in[0];
    const float* feats = (const float*)d_in[1];
    const float* masks = (const float*)d_in[2];
    const float* W1  = (const float*)d_in[3];
    const float* b1  = (const float*)d_in[4];
    const float* g1  = (const float*)d_in[5];
    const float* be1 = (const float*)d_in[6];
    const float* W2  = (const float*)d_in[7];
    const float* b2  = (const float*)d_in[8];
    const float* g2  = (const float*)d_in[9];
    const float* be2 = (const float*)d_in[10];
    const float* W3  = (const float*)d_in[11];
    const float* b3  = (const float*)d_in[12];
    const float* g3  = (const float*)d_in[13];
    const float* be3 = (const float*)d_in[14];
    const float* W4  = (const float*)d_in[15];

    cudaFuncSetAttribute(stageB, cudaFuncAttributeMaxDynamicSharedMemorySize, DSMEM_BYTES);
    cudaFuncSetAttribute(stageC, cudaFuncAttributeMaxDynamicSharedMemorySize, DSMEM_BYTES);

    prepW<<<256, 256>>>(W2, W3);
    stageA<<<BV, 256>>>(xyz, masks);
    stageB<<<NBLK, 512, DSMEM_BYTES>>>(xyz, W1, b1, g1, be1, b2, g2, be2);
    stageG<<<BV, CP>>>(W3, b3);
    stageC<<<NBLK, 512, DSMEM_BYTES>>>(feats, masks, g3, be3, W4);
    stageD<<<BV, CP>>>((float*)d_out);
}

// round 6
// speedup vs baseline: 2.7753x; 1.0760x over previous
#include <cuda_runtime.h>
#include <cuda_bf16.h>
#include <cstdint>
#include <math.h>

#define BB 8
#define VV 4
#define NPTS 16384
#define CP 256
#define BV 32
#define TM 128
#define NTILES 128
#define NBLK (BV*NTILES)      // 4096
#define EPS 1e-5f

// ---------------- device scratch ----------------
__device__ float    g_center[BV*3];
__device__ float    g_diam[BV];
__device__ unsigned g_gmaxu[BV*CP];
__device__ float    g_gcon[BV*CP];
// prepped weights: [8 chunks][256 n][20 words] u32 (16 payload + 4 pad), stride-80B rows
__device__ __align__(16) unsigned gW2h[40960], gW2l[40960];
__device__ __align__(16) unsigned gW3h[40960], gW3l[40960];
// local features, stored as the exact A-operand smem image per tile: [tile][16384 u32]
__device__ __align__(16) unsigned g_localH[(size_t)NBLK*16384];
__device__ __align__(16) unsigned g_localL[(size_t)NBLK*16384];
__device__ float    g_poolpart[(size_t)NBLK*CP];
__device__ float    g_denpart[NBLK];

// ---------------- helpers ----------------
__device__ __forceinline__ unsigned fkey(float f) {
    unsigned u = __float_as_uint(f);
    return (u & 0x80000000u) ? ~u : (u | 0x80000000u);
}
__device__ __forceinline__ float fdec(unsigned k) {
    return __uint_as_float((k & 0x80000000u) ? (k ^ 0x80000000u) : ~k);
}
__device__ __forceinline__ unsigned short bfbits(__nv_bfloat16 h) {
    union { __nv_bfloat16 b; unsigned short u; } x; x.b = h; return x.u;
}
__device__ __forceinline__ void split_bf(float y, unsigned short& h, unsigned short& l) {
    __nv_bfloat16 hb = __float2bfloat16(y);
    float hr = __bfloat162float(hb);
    __nv_bfloat16 lb = __float2bfloat16(y - hr);
    h = bfbits(hb); l = bfbits(lb);
}
// A smem swizzle at 16B-slot granularity: keeps every slot 16B-aligned (ldmatrix-safe)
__device__ __forceinline__ unsigned physA(unsigned w, unsigned row) {
    unsigned sw = w >> 2;
    unsigned ps = (sw ^ (row & 7u) ^ (sw >> 3)) & 31u;
    return ps * 4u + (w & 3u);
}
__device__ __forceinline__ uint32_t smem_u32(const void* p) {
    uint32_t a;
    asm("{ .reg .u64 tmp; cvta.to.shared.u64 tmp, %1; cvt.u32.u64 %0, tmp; }" : "=r"(a) : "l"(p));
    return a;
}
__device__ __forceinline__ void mma16816(float* d, const unsigned* a, const unsigned* b) {
    asm volatile(
        "mma.sync.aligned.m16n8k16.row.col.f32.bf16.bf16.f32 "
        "{%0,%1,%2,%3}, {%4,%5,%6,%7}, {%8,%9}, {%0,%1,%2,%3};"
        : "+f"(d[0]), "+f"(d[1]), "+f"(d[2]), "+f"(d[3])
        : "r"(a[0]), "r"(a[1]), "r"(a[2]), "r"(a[3]), "r"(b[0]), "r"(b[1]));
}
__device__ __forceinline__ void ldsm4(unsigned* r, uint32_t a) {
    asm volatile("ldmatrix.sync.aligned.m8n8.x4.shared.b16 {%0,%1,%2,%3}, [%4];"
        : "=r"(r[0]), "=r"(r[1]), "=r"(r[2]), "=r"(r[3]) : "r"(a));
}
__device__ __forceinline__ void cp16(uint32_t dst, const void* src) {
    asm volatile("cp.async.cg.shared.global [%0], [%1], 16;" :: "r"(dst), "l"(src));
}

// dynamic smem: AH 16384 u32 | AL 16384 | B: 2 buffers x (BH 5120 + BL 5120) = 53248 u32 = 208KB
#define B_REGION_OFF 32768
#define DSMEM_U32 (32768 + 4*5120)
#define DSMEM_BYTES (DSMEM_U32*4)

// ---------------- prep: split + transpose into stride-80B chunked layout ----------------
__global__ void prepW(const float* __restrict__ W2, const float* __restrict__ W3) {
    int idx = blockIdx.x * 256 + threadIdx.x;   // 0..81919
    int mat = idx / 40960;
    int e = idx % 40960;
    int ck = e / 5120;
    int r = e % 5120;
    int n = r / 20, w = r % 20;
    unsigned hw = 0u, lw = 0u;
    if (w < 16) {
        int k = ck * 32 + w * 2;
        const float* W = mat ? W3 : W2;
        float v0 = W[k * CP + n], v1 = W[(k + 1) * CP + n];
        unsigned short h0, l0, h1, l1;
        split_bf(v0, h0, l0); split_bf(v1, h1, l1);
        hw = (unsigned)h0 | ((unsigned)h1 << 16);
        lw = (unsigned)l0 | ((unsigned)l1 << 16);
    }
    int dst = ck * 5120 + n * 20 + w;
    if (mat) { gW3h[dst] = hw; gW3l[dst] = lw; }
    else     { gW2h[dst] = hw; gW2l[dst] = lw; }
}

// ---------------- stage A: per-(b,v) center / diam ----------------
__global__ void stageA(const float* __restrict__ xyz, const float* __restrict__ masks) {
    int bv = blockIdx.x, b = bv >> 2, t = threadIdx.x;
    const float* xp = xyz + (size_t)b * 3 * NPTS;
    const float* mp = masks + (size_t)bv * NPTS;
    float s0 = 0.f, s1 = 0.f, s2 = 0.f, s3 = 0.f;
    float mn0 = 1e30f, mn1 = 1e30f, mn2 = 1e30f;
    float mx0 = -1e30f, mx1 = -1e30f, mx2 = -1e30f;
    for (int n = t; n < NPTS; n += 256) {
        float m = mp[n];
        float x = xp[n] * m, y = xp[NPTS + n] * m, z = xp[2 * NPTS + n] * m;
        s0 += x; s1 += y; s2 += z; s3 += m;
        mn0 = fminf(mn0, x); mx0 = fmaxf(mx0, x);
        mn1 = fminf(mn1, y); mx1 = fmaxf(mx1, y);
        mn2 = fminf(mn2, z); mx2 = fmaxf(mx2, z);
    }
    #pragma unroll
    for (int off = 16; off; off >>= 1) {
        s0 += __shfl_xor_sync(~0u, s0, off);
        s1 += __shfl_xor_sync(~0u, s1, off);
        s2 += __shfl_xor_sync(~0u, s2, off);
        s3 += __shfl_xor_sync(~0u, s3, off);
        mn0 = fminf(mn0, __shfl_xor_sync(~0u, mn0, off));
        mn1 = fminf(mn1, __shfl_xor_sync(~0u, mn1, off));
        mn2 = fminf(mn2, __shfl_xor_sync(~0u, mn2, off));
        mx0 = fmaxf(mx0, __shfl_xor_sync(~0u, mx0, off));
        mx1 = fmaxf(mx1, __shfl_xor_sync(~0u, mx1, off));
        mx2 = fmaxf(mx2, __shfl_xor_sync(~0u, mx2, off));
    }
    __shared__ float rb[8][10];
    int wid = t >> 5, lane = t & 31;
    if (lane == 0) {
        rb[wid][0] = s0; rb[wid][1] = s1; rb[wid][2] = s2; rb[wid][3] = s3;
        rb[wid][4] = mn0; rb[wid][5] = mn1; rb[wid][6] = mn2;
        rb[wid][7] = mx0; rb[wid][8] = mx1; rb[wid][9] = mx2;
    }
    __syncthreads();
    if (t == 0) {
        float S0 = 0, S1 = 0, S2 = 0, S3 = 0;
        float MN0 = 1e30f, MN1 = 1e30f, MN2 = 1e30f;
        float MX0 = -1e30f, MX1 = -1e30f, MX2 = -1e30f;
        for (int w = 0; w < 8; w++) {
            S0 += rb[w][0]; S1 += rb[w][1]; S2 += rb[w][2]; S3 += rb[w][3];
            MN0 = fminf(MN0, rb[w][4]); MN1 = fminf(MN1, rb[w][5]); MN2 = fminf(MN2, rb[w][6]);
            MX0 = fmaxf(MX0, rb[w][7]); MX1 = fmaxf(MX1, rb[w][8]); MX2 = fmaxf(MX2, rb[w][9]);
        }
        float valid = fmaxf(S3, 1.f);
        g_center[bv * 3 + 0] = S0 / valid;
        g_center[bv * 3 + 1] = S1 / valid;
        g_center[bv * 3 + 2] = S2 / valid;
        float d = fmaxf(fmaxf(MX0 - MN0, MX1 - MN1), MX2 - MN2);
        g_diam[bv] = (d == 0.f) ? 1.f : d;
    }
    g_gmaxu[bv * CP + t] = 0u;
}

// ---------------- copy one B chunk (hi+lo, 2x20KB) via cp.async ----------------
__device__ __forceinline__ void cp_chunk(uint32_t bh_a, uint32_t bl_a,
                                         const unsigned* srcH, const unsigned* srcL, int t) {
    #pragma unroll
    for (int i = 0; i < 3; i++) {
        int idx = t + i * 512;
        if (idx < 1280) {
            cp16(bh_a + idx * 16, srcH + idx * 4);
            cp16(bl_a + idx * 16, srcL + idx * 4);
        }
    }
}

// ---------------- shared mainloop: ldmatrix + cp.async double-buffered B ----------------
__device__ __forceinline__ void gemm_mainloop(
    uint32_t aH_a, uint32_t aL_a, uint32_t b_a,
    const unsigned* gWh, const unsigned* gWl,
    float* acc, int t, int lane, int m0w, int n0w)
{
    int la7 = lane & 7;
    int rA0 = m0w + ((lane >> 3) & 1) * 8 + la7;     // mi=0 base row
    int wselA = ((lane >> 4) & 1) * 4;
    int rB_off = ((lane >> 4) & 1) * 8 + la7;
    unsigned wselB = (unsigned)(((lane >> 3) & 1) * 4);
    unsigned rowB80[4];
    #pragma unroll
    for (int p = 0; p < 4; p++) rowB80[p] = (unsigned)(n0w + p * 16 + rB_off) * 80u;

    // prologue: chunk 0 -> buffer 0
    cp_chunk(b_a, b_a + 20480u, gWh, gWl, t);
    asm volatile("cp.async.commit_group;" ::: "memory");

    #pragma unroll 1
    for (int ck = 0; ck < 8; ck++) {
        uint32_t bufh = b_a + (unsigned)(ck & 1) * 40960u;
        uint32_t bufl = bufh + 20480u;
        asm volatile("cp.async.wait_group 0;" ::: "memory");
        __syncthreads();   // chunk ck visible; prev compute done before next copy lands
        if (ck < 7) {
            uint32_t nb = b_a + (unsigned)((ck + 1) & 1) * 40960u;
            cp_chunk(nb, nb + 20480u, gWh + (ck + 1) * 5120, gWl + (ck + 1) * 5120, t);
            asm volatile("cp.async.commit_group;" ::: "memory");
        }
        #pragma unroll
        for (int kk = 0; kk < 2; kk++) {
            int w0 = ck * 16 + kk * 8;
            unsigned ah[2][4], al[2][4];
            #pragma unroll
            for (int mi = 0; mi < 2; mi++) {
                int row = rA0 + mi * 16;
                unsigned w = (unsigned)(w0 + wselA);
                uint32_t off = (unsigned)row * 512u + physA(w, (unsigned)row) * 4u;
                ldsm4(ah[mi], aH_a + off);
                ldsm4(al[mi], aL_a + off);
            }
            uint32_t woffB = ((unsigned)(kk * 8) + wselB) * 4u;
            #pragma unroll
            for (int p = 0; p < 4; p++) {
                unsigned bh[4], bl[4];
                ldsm4(bh, bufh + rowB80[p] + woffB);
                ldsm4(bl, bufl + rowB80[p] + woffB);
                #pragma unroll
                for (int mi = 0; mi < 2; mi++) {
                    float* d0 = acc + mi * 32 + (2 * p) * 4;
                    float* d1 = acc + mi * 32 + (2 * p + 1) * 4;
                    mma16816(d0, ah[mi], bh);
                    mma16816(d0, al[mi], bh);
                    mma16816(d0, ah[mi], bl);
                    mma16816(d1, ah[mi], bh + 2);
                    mma16816(d1, al[mi], bh + 2);
                    mma16816(d1, ah[mi], bl + 2);
                }
            }
        }
    }
}

// ---------------- stage B ----------------
__global__ __launch_bounds__(512, 1) void stageB(
    const float* __restrict__ xyz,
    const float* __restrict__ W1, const float* __restrict__ b1,
    const float* __restrict__ g1v, const float* __restrict__ be1,
    const float* __restrict__ b2, const float* __restrict__ g2v,
    const float* __restrict__ be2)
{
    extern __shared__ unsigned smu[];
    unsigned* AH = smu;
    unsigned* AL = smu + 16384;
    __shared__ float W1s[3 * CP], b1s[CP], g1s[CP], be1s[CP], b2s[CP], g2s[CP], be2s[CP];
    __shared__ float rr_s[TM][4], rr_s2[TM][4], mean_s[TM], inv_s[TM];

    int t = threadIdx.x, lane = t & 31, wid = t >> 5;
    int g = lane >> 2, r4 = lane & 3;
    int bv = blockIdx.x >> 7, tile = blockIdx.x & 127;
    int b = bv >> 2, n0 = tile * TM;

    uint32_t aH_a = smem_u32(AH), aL_a = smem_u32(AL), b_a = smem_u32(smu + B_REGION_OFF);

    for (int i = t; i < CP; i += 512) {
        W1s[i] = W1[i]; W1s[CP + i] = W1[CP + i]; W1s[2 * CP + i] = W1[2 * CP + i];
        b1s[i] = b1[i]; g1s[i] = g1v[i]; be1s[i] = be1[i];
        b2s[i] = b2[i]; g2s[i] = g2v[i]; be2s[i] = be2[i];
    }

    // ---- pass 1: relu(LN(xyzn@W1+b1)) -> A operand in smem ----
    int m = t >> 2, q = t & 3;
    float cx = g_center[bv * 3 + 0], cy = g_center[bv * 3 + 1], cz = g_center[bv * 3 + 2];
    float dinv = 1.f / g_diam[bv];
    const float* xp = xyz + (size_t)b * 3 * NPTS;
    float sx = (xp[n0 + m] - cx) * dinv;
    float sy = (xp[NPTS + n0 + m] - cy) * dinv;
    float sz = (xp[2 * NPTS + n0 + m] - cz) * dinv;
    __syncthreads();

    {
        float v[64]; float s = 0.f, s2 = 0.f;
        #pragma unroll
        for (int i = 0; i < 64; i++) {
            int c = q * 64 + i;
            v[i] = fmaf(sx, W1s[c], fmaf(sy, W1s[CP + c], fmaf(sz, W1s[2 * CP + c], b1s[c])));
            s += v[i]; s2 += v[i] * v[i];
        }
        s  += __shfl_xor_sync(~0u, s, 1);  s  += __shfl_xor_sync(~0u, s, 2);
        s2 += __shfl_xor_sync(~0u, s2, 1); s2 += __shfl_xor_sync(~0u, s2, 2);
        float mu = s * (1.f / CP);
        float var = s2 * (1.f / CP) - mu * mu;
        float iv = rsqrtf(var + EPS);
        #pragma unroll
        for (int i = 0; i < 64; i += 2) {
            int c = q * 64 + i;
            float y0 = fmaxf((v[i] - mu) * iv * g1s[c] + be1s[c], 0.f);
            float y1 = fmaxf((v[i + 1] - mu) * iv * g1s[c + 1] + be1s[c + 1], 0.f);
            unsigned short h0, l0, h1, l1;
            split_bf(y0, h0, l0); split_bf(y1, h1, l1);
            unsigned w = (unsigned)(c >> 1);
            unsigned idx = (unsigned)m * 128u + physA(w, (unsigned)m);
            AH[idx] = (unsigned)h0 | ((unsigned)h1 << 16);
            AL[idx] = (unsigned)l0 | ((unsigned)l1 << 16);
        }
    }

    // ---- mainloop ----
    int m0w = (wid & 3) * 32, n0w = (wid >> 2) * 64;
    float acc[64];
    #pragma unroll
    for (int i = 0; i < 64; i++) acc[i] = 0.f;
    gemm_mainloop(aH_a, aL_a, b_a, gW2h, gW2l, acc, t, lane, m0w, n0w);

    // ---- epilogue: +b2, LN2, col-max, split -> staged smem -> g_local ----
    int wn = wid >> 2;
    #pragma unroll
    for (int mh = 0; mh < 4; mh++) {
        int mi = mh >> 1, h = mh & 1;
        int row = m0w + mi * 16 + g + 8 * h;
        float s = 0.f, s2 = 0.f;
        #pragma unroll
        for (int ni = 0; ni < 8; ni++) {
            #pragma unroll
            for (int r01 = 0; r01 < 2; r01++) {
                int c = n0w + ni * 8 + r4 * 2 + r01;
                float vv = acc[mi * 32 + ni * 4 + 2 * h + r01] + b2s[c];
                s += vv; s2 += vv * vv;
            }
        }
        s  += __shfl_xor_sync(~0u, s, 1);  s  += __shfl_xor_sync(~0u, s, 2);
        s2 += __shfl_xor_sync(~0u, s2, 1); s2 += __shfl_xor_sync(~0u, s2, 2);
        if (r4 == 0) { rr_s[row][wn] = s; rr_s2[row][wn] = s2; }
    }
    __syncthreads();
    if (t < TM) {
        float S = rr_s[t][0] + rr_s[t][1] + rr_s[t][2] + rr_s[t][3];
        float S2 = rr_s2[t][0] + rr_s2[t][1] + rr_s2[t][2] + rr_s2[t][3];
        float mu = S * (1.f / CP);
        float var = S2 * (1.f / CP) - mu * mu;
        mean_s[t] = mu; inv_s[t] = rsqrtf(var + EPS);
    }
    __syncthreads();

    float cmax[16];
    #pragma unroll
    for (int j = 0; j < 16; j++) cmax[j] = -1e30f;
    #pragma unroll
    for (int mh = 0; mh < 4; mh++) {
        int mi = mh >> 1, h = mh & 1;
        int row = m0w + mi * 16 + g + 8 * h;
        float mu = mean_s[row], iv = inv_s[row];
        #pragma unroll
        for (int ni = 0; ni < 8; ni++) {
            int c0 = n0w + ni * 8 + r4 * 2;
            float y0 = (acc[mi * 32 + ni * 4 + 2 * h] + b2s[c0] - mu) * iv * g2s[c0] + be2s[c0];
            float y1 = (acc[mi * 32 + ni * 4 + 2 * h + 1] + b2s[c0 + 1] - mu) * iv * g2s[c0 + 1] + be2s[c0 + 1];
            cmax[ni * 2]     = fmaxf(cmax[ni * 2], y0);
            cmax[ni * 2 + 1] = fmaxf(cmax[ni * 2 + 1], y1);
            unsigned short h0, l0, h1, l1;
            split_bf(y0, h0, l0); split_bf(y1, h1, l1);
            unsigned w = (unsigned)((n0w >> 1) + ni * 4 + r4);
            unsigned idx = (unsigned)row * 128u + physA(w, (unsigned)row);
            AH[idx] = (unsigned)h0 | ((unsigned)h1 << 16);
            AL[idx] = (unsigned)l0 | ((unsigned)l1 << 16);
        }
    }
    #pragma unroll
    for (int j = 0; j < 16; j++) {
        cmax[j] = fmaxf(cmax[j], __shfl_xor_sync(~0u, cmax[j], 4));
        cmax[j] = fmaxf(cmax[j], __shfl_xor_sync(~0u, cmax[j], 8));
        cmax[j] = fmaxf(cmax[j], __shfl_xor_sync(~0u, cmax[j], 16));
    }
    if (lane < 4) {
        #pragma unroll
        for (int ni = 0; ni < 8; ni++) {
            int c0 = n0w + ni * 8 + lane * 2;
            atomicMax(&g_gmaxu[bv * CP + c0], fkey(cmax[ni * 2]));
            atomicMax(&g_gmaxu[bv * CP + c0 + 1], fkey(cmax[ni * 2 + 1]));
        }
    }
    __syncthreads();
    {
        size_t gb = (size_t)blockIdx.x * 16384;
        uint4* dh = (uint4*)(g_localH + gb);
        uint4* dl = (uint4*)(g_localL + gb);
        const uint4* sh = (const uint4*)AH;
        const uint4* sl = (const uint4*)AL;
        #pragma unroll
        for (int i = 0; i < 8; i++) { dh[t + i * 512] = sh[t + i * 512]; dl[t + i * 512] = sl[t + i * 512]; }
    }
}

// ---------------- stage G: gcon = b3 + global @ W3[256:512] (widened) ----------------
__global__ void stageG(const float* __restrict__ W3, const float* __restrict__ b3) {
    __shared__ float gsm[CP];
    __shared__ float part[8][32];
    int bv = blockIdx.x >> 3, seg = blockIdx.x & 7;
    int t = threadIdx.x;
    gsm[t] = fdec(g_gmaxu[bv * CP + t]);
    __syncthreads();
    int c = seg * 32 + (t & 31), jg = t >> 5;
    float a = 0.f;
    #pragma unroll 4
    for (int j = jg * 32; j < jg * 32 + 32; j++) a = fmaf(gsm[j], W3[(CP + j) * CP + c], a);
    part[jg][t & 31] = a;
    __syncthreads();
    if (t < 32) {
        float s = b3[seg * 32 + t];
        #pragma unroll
        for (int w = 0; w < 8; w++) s += part[w][t];
        g_gcon[bv * CP + seg * 32 + t] = s;
    }
}

// ---------------- stage C ----------------
__global__ __launch_bounds__(512, 1) void stageC(
    const float* __restrict__ feats, const float* __restrict__ masks,
    const float* __restrict__ g3v, const float* __restrict__ be3,
    const float* __restrict__ W4)
{
    extern __shared__ unsigned smu[];
    unsigned* AH = smu;
    unsigned* AL = smu + 16384;
    __shared__ float gcs[CP], g3s[CP], be3s[CP], W4s[CP];
    __shared__ float rr_s[TM][4], rr_s2[TM][4], mean_s[TM], inv_s[TM];
    __shared__ __align__(16) float mw_s[TM];

    int t = threadIdx.x, lane = t & 31, wid = t >> 5;
    int g = lane >> 2, r4 = lane & 3;
    int bv = blockIdx.x >> 7, tile = blockIdx.x & 127;
    int b = bv >> 2, n0 = tile * TM;

    uint32_t aH_a = smem_u32(AH), aL_a = smem_u32(AL), b_a = smem_u32(smu + B_REGION_OFF);

    for (int i = t; i < CP; i += 512) {
        gcs[i] = g_gcon[bv * CP + i];
        g3s[i] = g3v[i]; be3s[i] = be3[i]; W4s[i] = W4[i];
    }
    {
        size_t gb = (size_t)blockIdx.x * 16384;
        const uint4* sh = (const uint4*)(g_localH + gb);
        const uint4* sl = (const uint4*)(g_localL + gb);
        uint4* dh = (uint4*)AH; uint4* dl = (uint4*)AL;
        #pragma unroll
        for (int i = 0; i < 8; i++) { dh[t + i * 512] = sh[t + i * 512]; dl[t + i * 512] = sl[t + i * 512]; }
    }

    int m0w = (wid & 3) * 32, n0w = (wid >> 2) * 64;
    float acc[64];
    #pragma unroll
    for (int i = 0; i < 64; i++) acc[i] = 0.f;
    gemm_mainloop(aH_a, aL_a, b_a, gW3h, gW3l, acc, t, lane, m0w, n0w);

    // ---- epilogue: +gcon, LN3, relu, dot W4, sigmoid -> mw ----
    int wn = wid >> 2;
    #pragma unroll
    for (int mh = 0; mh < 4; mh++) {
        int mi = mh >> 1, h = mh & 1;
        int row = m0w + mi * 16 + g + 8 * h;
        float s = 0.f, s2 = 0.f;
        #pragma unroll
        for (int ni = 0; ni < 8; ni++) {
            #pragma unroll
            for (int r01 = 0; r01 < 2; r01++) {
                int c = n0w + ni * 8 + r4 * 2 + r01;
                float vv = acc[mi * 32 + ni * 4 + 2 * h + r01] + gcs[c];
                s += vv; s2 += vv * vv;
            }
        }
        s  += __shfl_xor_sync(~0u, s, 1);  s  += __shfl_xor_sync(~0u, s, 2);
        s2 += __shfl_xor_sync(~0u, s2, 1); s2 += __shfl_xor_sync(~0u, s2, 2);
        if (r4 == 0) { rr_s[row][wn] = s; rr_s2[row][wn] = s2; }
    }
    __syncthreads();
    if (t < TM) {
        float S = rr_s[t][0] + rr_s[t][1] + rr_s[t][2] + rr_s[t][3];
        float S2 = rr_s2[t][0] + rr_s2[t][1] + rr_s2[t][2] + rr_s2[t][3];
        float mu = S * (1.f / CP);
        float var = S2 * (1.f / CP) - mu * mu;
        mean_s[t] = mu; inv_s[t] = rsqrtf(var + EPS);
    }
    __syncthreads();
    #pragma unroll
    for (int mh = 0; mh < 4; mh++) {
        int mi = mh >> 1, h = mh & 1;
        int row = m0w + mi * 16 + g + 8 * h;
        float mu = mean_s[row], iv = inv_s[row];
        float dp = 0.f;
        #pragma unroll
        for (int ni = 0; ni < 8; ni++) {
            #pragma unroll
            for (int r01 = 0; r01 < 2; r01++) {
                int c = n0w + ni * 8 + r4 * 2 + r01;
                float y = fmaxf((acc[mi * 32 + ni * 4 + 2 * h + r01] + gcs[c] - mu) * iv * g3s[c] + be3s[c], 0.f);
                dp = fmaf(y, W4s[c], dp);
            }
        }
        dp += __shfl_xor_sync(~0u, dp, 1); dp += __shfl_xor_sync(~0u, dp, 2);
        if (r4 == 0) rr_s[row][wn] = dp;
    }
    __syncthreads();
    if (t < TM) {
        float dpv = rr_s[t][0] + rr_s[t][1] + rr_s[t][2] + rr_s[t][3];
        float w = 2.f / (1.f + expf(-dpv));
        mw_s[t] = w * masks[(size_t)bv * NPTS + n0 + t];
    }
    __syncthreads();

    // ---- pooling: warp per 16 channels ----
    const float* fb = feats + (size_t)b * CP * NPTS;
    float4 m4 = ((const float4*)mw_s)[lane];
    #pragma unroll 1
    for (int ci = 0; ci < 16; ci++) {
        int c = wid * 16 + ci;
        float4 f = *(const float4*)(fb + (size_t)c * NPTS + n0 + lane * 4);
        float p = f.x * m4.x + f.y * m4.y + f.z * m4.z + f.w * m4.w;
        #pragma unroll
        for (int off = 16; off; off >>= 1) p += __shfl_xor_sync(~0u, p, off);
        if (lane == 0) g_poolpart[(size_t)blockIdx.x * CP + c] = p;
    }
    if (wid == 0) {
        float d = mw_s[lane] + mw_s[lane + 32] + mw_s[lane + 64] + mw_s[lane + 96];
        #pragma unroll
        for (int off = 16; off; off >>= 1) d += __shfl_xor_sync(~0u, d, off);
        if (lane == 0) g_denpart[blockIdx.x] = d;
    }
}

// ---------------- stage D: final reduce ----------------
__global__ void stageD(float* __restrict__ out) {
    int bv = blockIdx.x, t = threadIdx.x;
    __shared__ float dsum_s;
    float p = 0.f;
    for (int tl = 0; tl < NTILES; tl++)
        p += g_poolpart[((size_t)(bv * NTILES + tl)) * CP + t];
    if (t == 0) {
        float d = 0.f;
        for (int tl = 0; tl < NTILES; tl++) d += g_denpart[bv * NTILES + tl];
        dsum_s = fmaxf(d, 1e-8f);
    }
    __syncthreads();
    out[bv * CP + t] = p / dsum_s + fdec(g_gmaxu[bv * CP + t]);
}

extern "C" void kernel_launch(void* const* d_in, const int* in_sizes, int n_in,
                              void* d_out, int out_size) {
    const float* xyz   = (const float*)d_in[0];
    const float* feats = (const float*)d_in[1];
    const float* masks = (const float*)d_in[2];
    const float* W1  = (const float*)d_in[3];
    const float* b1  = (const float*)d_in[4];
    const float* g1  = (const float*)d_in[5];
    const float* be1 = (const float*)d_in[6];
    const float* W2  = (const float*)d_in[7];
    const float* b2  = (const float*)d_in[8];
    const float* g2  = (const float*)d_in[9];
    const float* be2 = (const float*)d_in[10];
    const float* W3  = (const float*)d_in[11];
    const float* b3  = (const float*)d_in[12];
    const float* g3  = (const float*)d_in[13];
    const float* be3 = (const float*)d_in[14];
    const float* W4  = (const float*)d_in[15];

    cudaFuncSetAttribute(stageB, cudaFuncAttributeMaxDynamicSharedMemorySize, DSMEM_BYTES);
    cudaFuncSetAttribute(stageC, cudaFuncAttributeMaxDynamicSharedMemorySize, DSMEM_BYTES);

    prepW<<<320, 256>>>(W2, W3);
    stageA<<<BV, 256>>>(xyz, masks);
    stageB<<<NBLK, 512, DSMEM_BYTES>>>(xyz, W1, b1, g1, be1, b2, g2, be2);
    stageG<<<BV * 8, 256>>>(W3, b3);
    stageC<<<NBLK, 512, DSMEM_BYTES>>>(feats, masks, g3, be3, W4);
    stageD<<<BV, CP>>>((float*)d_out);
}

// round 7
// speedup vs baseline: 3.5202x; 1.2684x over previous
#include <cuda_runtime.h>
#include <cuda_fp16.h>
#include <cstdint>
#include <math.h>

#define BB 8
#define VV 4
#define NPTS 16384
#define CP 256
#define BV 32
#define TM 128
#define NTILES 128
#define NBLK (BV*NTILES)      // 4096
#define EPS 1e-5f

// ---------------- device scratch ----------------
__device__ float    g_center[BV*3];
__device__ float    g_diam[BV];
__device__ unsigned g_gmaxu[BV*CP];
__device__ float    g_gcon[BV*CP];
// prepped weights (fp16 hi/lo): [8 chunks][256 n][20 words] u32, stride-80B rows
__device__ __align__(16) unsigned gW2h[40960], gW2l[40960];
__device__ __align__(16) unsigned gW3h[40960], gW3l[40960];
// local features (single fp16), stored as the exact A-operand smem image: [tile][16384 u32]
__device__ __align__(16) unsigned g_localH[(size_t)NBLK*16384];
__device__ float    g_poolpart[(size_t)NBLK*CP];
__device__ float    g_denpart[NBLK];

// ---------------- helpers ----------------
__device__ __forceinline__ unsigned fkey(float f) {
    unsigned u = __float_as_uint(f);
    return (u & 0x80000000u) ? ~u : (u | 0x80000000u);
}
__device__ __forceinline__ float fdec(unsigned k) {
    return __uint_as_float((k & 0x80000000u) ? (k ^ 0x80000000u) : ~k);
}
__device__ __forceinline__ unsigned short hbits(__half h) {
    union { __half b; unsigned short u; } x; x.b = h; return x.u;
}
__device__ __forceinline__ void split_h(float y, unsigned short& h, unsigned short& l) {
    __half hb = __float2half_rn(y);
    float hr = __half2float(hb);
    __half lb = __float2half_rn(y - hr);
    h = hbits(hb); l = hbits(lb);
}
// A smem swizzle at 16B-slot granularity (ldmatrix-safe)
__device__ __forceinline__ unsigned physA(unsigned w, unsigned row) {
    unsigned sw = w >> 2;
    unsigned ps = (sw ^ (row & 7u) ^ (sw >> 3)) & 31u;
    return ps * 4u + (w & 3u);
}
__device__ __forceinline__ uint32_t smem_u32(const void* p) {
    uint32_t a;
    asm("{ .reg .u64 tmp; cvta.to.shared.u64 tmp, %1; cvt.u32.u64 %0, tmp; }" : "=r"(a) : "l"(p));
    return a;
}
__device__ __forceinline__ void mma16816(float* d, const unsigned* a, const unsigned* b) {
    asm volatile(
        "mma.sync.aligned.m16n8k16.row.col.f32.f16.f16.f32 "
        "{%0,%1,%2,%3}, {%4,%5,%6,%7}, {%8,%9}, {%0,%1,%2,%3};"
        : "+f"(d[0]), "+f"(d[1]), "+f"(d[2]), "+f"(d[3])
        : "r"(a[0]), "r"(a[1]), "r"(a[2]), "r"(a[3]), "r"(b[0]), "r"(b[1]));
}
__device__ __forceinline__ void ldsm4(unsigned* r, uint32_t a) {
    asm volatile("ldmatrix.sync.aligned.m8n8.x4.shared.b16 {%0,%1,%2,%3}, [%4];"
        : "=r"(r[0]), "=r"(r[1]), "=r"(r[2]), "=r"(r[3]) : "r"(a));
}
__device__ __forceinline__ void cp16(uint32_t dst, const void* src) {
    asm volatile("cp.async.cg.shared.global [%0], [%1], 16;" :: "r"(dst), "l"(src));
}

// dynamic smem: AH 16384 u32 | B: 2 buffers x (BH 5120 + BL 5120) u32 = 144KB
#define B_REGION_OFF 16384
#define DSMEM_U32 (16384 + 4*5120)
#define DSMEM_BYTES (DSMEM_U32*4)

// ---------------- stage A+prep merged: blocks 0..319 prep weights, 320..351 centers ----------------
__global__ void stageAP(const float* __restrict__ W2, const float* __restrict__ W3,
                        const float* __restrict__ xyz, const float* __restrict__ masks) {
    if (blockIdx.x < 320) {
        int idx = blockIdx.x * 256 + threadIdx.x;   // 0..81919
        int mat = idx / 40960;
        int e = idx % 40960;
        int ck = e / 5120;
        int r = e % 5120;
        int n = r / 20, w = r % 20;
        unsigned hw = 0u, lw = 0u;
        if (w < 16) {
            int k = ck * 32 + w * 2;
            const float* W = mat ? W3 : W2;
            float v0 = W[k * CP + n], v1 = W[(k + 1) * CP + n];
            unsigned short h0, l0, h1, l1;
            split_h(v0, h0, l0); split_h(v1, h1, l1);
            hw = (unsigned)h0 | ((unsigned)h1 << 16);
            lw = (unsigned)l0 | ((unsigned)l1 << 16);
        }
        int dst = ck * 5120 + n * 20 + w;
        if (mat) { gW3h[dst] = hw; gW3l[dst] = lw; }
        else     { gW2h[dst] = hw; gW2l[dst] = lw; }
        return;
    }
    int bv = blockIdx.x - 320, b = bv >> 2, t = threadIdx.x;
    const float* xp = xyz + (size_t)b * 3 * NPTS;
    const float* mp = masks + (size_t)bv * NPTS;
    float s0 = 0.f, s1 = 0.f, s2 = 0.f, s3 = 0.f;
    float mn0 = 1e30f, mn1 = 1e30f, mn2 = 1e30f;
    float mx0 = -1e30f, mx1 = -1e30f, mx2 = -1e30f;
    for (int n = t; n < NPTS; n += 256) {
        float m = mp[n];
        float x = xp[n] * m, y = xp[NPTS + n] * m, z = xp[2 * NPTS + n] * m;
        s0 += x; s1 += y; s2 += z; s3 += m;
        mn0 = fminf(mn0, x); mx0 = fmaxf(mx0, x);
        mn1 = fminf(mn1, y); mx1 = fmaxf(mx1, y);
        mn2 = fminf(mn2, z); mx2 = fmaxf(mx2, z);
    }
    #pragma unroll
    for (int off = 16; off; off >>= 1) {
        s0 += __shfl_xor_sync(~0u, s0, off);
        s1 += __shfl_xor_sync(~0u, s1, off);
        s2 += __shfl_xor_sync(~0u, s2, off);
        s3 += __shfl_xor_sync(~0u, s3, off);
        mn0 = fminf(mn0, __shfl_xor_sync(~0u, mn0, off));
        mn1 = fminf(mn1, __shfl_xor_sync(~0u, mn1, off));
        mn2 = fminf(mn2, __shfl_xor_sync(~0u, mn2, off));
        mx0 = fmaxf(mx0, __shfl_xor_sync(~0u, mx0, off));
        mx1 = fmaxf(mx1, __shfl_xor_sync(~0u, mx1, off));
        mx2 = fmaxf(mx2, __shfl_xor_sync(~0u, mx2, off));
    }
    __shared__ float rb[8][10];
    int wid = t >> 5, lane = t & 31;
    if (lane == 0) {
        rb[wid][0] = s0; rb[wid][1] = s1; rb[wid][2] = s2; rb[wid][3] = s3;
        rb[wid][4] = mn0; rb[wid][5] = mn1; rb[wid][6] = mn2;
        rb[wid][7] = mx0; rb[wid][8] = mx1; rb[wid][9] = mx2;
    }
    __syncthreads();
    if (t == 0) {
        float S0 = 0, S1 = 0, S2 = 0, S3 = 0;
        float MN0 = 1e30f, MN1 = 1e30f, MN2 = 1e30f;
        float MX0 = -1e30f, MX1 = -1e30f, MX2 = -1e30f;
        for (int w = 0; w < 8; w++) {
            S0 += rb[w][0]; S1 += rb[w][1]; S2 += rb[w][2]; S3 += rb[w][3];
            MN0 = fminf(MN0, rb[w][4]); MN1 = fminf(MN1, rb[w][5]); MN2 = fminf(MN2, rb[w][6]);
            MX0 = fmaxf(MX0, rb[w][7]); MX1 = fmaxf(MX1, rb[w][8]); MX2 = fmaxf(MX2, rb[w][9]);
        }
        float valid = fmaxf(S3, 1.f);
        g_center[bv * 3 + 0] = S0 / valid;
        g_center[bv * 3 + 1] = S1 / valid;
        g_center[bv * 3 + 2] = S2 / valid;
        float d = fmaxf(fmaxf(MX0 - MN0, MX1 - MN1), MX2 - MN2);
        g_diam[bv] = (d == 0.f) ? 1.f : d;
    }
    g_gmaxu[bv * CP + t] = 0u;
}

// ---------------- copy one B chunk (hi+lo, 2x20KB) via cp.async ----------------
__device__ __forceinline__ void cp_chunk(uint32_t bh_a, uint32_t bl_a,
                                         const unsigned* srcH, const unsigned* srcL, int t) {
    #pragma unroll
    for (int i = 0; i < 3; i++) {
        int idx = t + i * 512;
        if (idx < 1280) {
            cp16(bh_a + idx * 16, srcH + idx * 4);
            cp16(bl_a + idx * 16, srcL + idx * 4);
        }
    }
}

// ---------------- shared mainloop: 2-term fp16 (A single, B hi/lo) ----------------
__device__ __forceinline__ void gemm_mainloop(
    uint32_t aH_a, uint32_t b_a,
    const unsigned* gWh, const unsigned* gWl,
    float* acc, int t, int lane, int m0w, int n0w)
{
    int la7 = lane & 7;
    int rA0 = m0w + ((lane >> 3) & 1) * 8 + la7;
    int wselA = ((lane >> 4) & 1) * 4;
    int rB_off = ((lane >> 4) & 1) * 8 + la7;
    unsigned wselB = (unsigned)(((lane >> 3) & 1) * 4);
    unsigned rowB80[4];
    #pragma unroll
    for (int p = 0; p < 4; p++) rowB80[p] = (unsigned)(n0w + p * 16 + rB_off) * 80u;

    cp_chunk(b_a, b_a + 20480u, gWh, gWl, t);
    asm volatile("cp.async.commit_group;" ::: "memory");

    #pragma unroll 1
    for (int ck = 0; ck < 8; ck++) {
        uint32_t bufh = b_a + (unsigned)(ck & 1) * 40960u;
        uint32_t bufl = bufh + 20480u;
        asm volatile("cp.async.wait_group 0;" ::: "memory");
        __syncthreads();
        if (ck < 7) {
            uint32_t nb = b_a + (unsigned)((ck + 1) & 1) * 40960u;
            cp_chunk(nb, nb + 20480u, gWh + (ck + 1) * 5120, gWl + (ck + 1) * 5120, t);
            asm volatile("cp.async.commit_group;" ::: "memory");
        }
        #pragma unroll
        for (int kk = 0; kk < 2; kk++) {
            int w0 = ck * 16 + kk * 8;
            unsigned ah[2][4];
            #pragma unroll
            for (int mi = 0; mi < 2; mi++) {
                int row = rA0 + mi * 16;
                unsigned w = (unsigned)(w0 + wselA);
                uint32_t off = (unsigned)row * 512u + physA(w, (unsigned)row) * 4u;
                ldsm4(ah[mi], aH_a + off);
            }
            uint32_t woffB = ((unsigned)(kk * 8) + wselB) * 4u;
            #pragma unroll
            for (int p = 0; p < 4; p++) {
                unsigned bh[4], bl[4];
                ldsm4(bh, bufh + rowB80[p] + woffB);
                ldsm4(bl, bufl + rowB80[p] + woffB);
                #pragma unroll
                for (int mi = 0; mi < 2; mi++) {
                    float* d0 = acc + mi * 32 + (2 * p) * 4;
                    float* d1 = acc + mi * 32 + (2 * p + 1) * 4;
                    mma16816(d0, ah[mi], bh);
                    mma16816(d0, ah[mi], bl);
                    mma16816(d1, ah[mi], bh + 2);
                    mma16816(d1, ah[mi], bl + 2);
                }
            }
        }
    }
}

// ---------------- stage B ----------------
__global__ __launch_bounds__(512, 1) void stageB(
    const float* __restrict__ xyz,
    const float* __restrict__ W1, const float* __restrict__ b1,
    const float* __restrict__ g1v, const float* __restrict__ be1,
    const float* __restrict__ b2, const float* __restrict__ g2v,
    const float* __restrict__ be2)
{
    extern __shared__ unsigned smu[];
    unsigned* AH = smu;
    __shared__ float W1s[3 * CP], b1s[CP], g1s[CP], be1s[CP], b2s[CP], g2s[CP], be2s[CP];
    __shared__ float rr_s[TM][4], rr_s2[TM][4], mean_s[TM], inv_s[TM];

    int t = threadIdx.x, lane = t & 31, wid = t >> 5;
    int g = lane >> 2, r4 = lane & 3;
    int bv = blockIdx.x >> 7, tile = blockIdx.x & 127;
    int b = bv >> 2, n0 = tile * TM;

    uint32_t aH_a = smem_u32(AH), b_a = smem_u32(smu + B_REGION_OFF);

    for (int i = t; i < CP; i += 512) {
        W1s[i] = W1[i]; W1s[CP + i] = W1[CP + i]; W1s[2 * CP + i] = W1[2 * CP + i];
        b1s[i] = b1[i]; g1s[i] = g1v[i]; be1s[i] = be1[i];
        b2s[i] = b2[i]; g2s[i] = g2v[i]; be2s[i] = be2[i];
    }

    // ---- pass 1: relu(LN(xyzn@W1+b1)) -> fp16 A operand in smem ----
    int m = t >> 2, q = t & 3;
    float cx = g_center[bv * 3 + 0], cy = g_center[bv * 3 + 1], cz = g_center[bv * 3 + 2];
    float dinv = 1.f / g_diam[bv];
    const float* xp = xyz + (size_t)b * 3 * NPTS;
    float sx = (xp[n0 + m] - cx) * dinv;
    float sy = (xp[NPTS + n0 + m] - cy) * dinv;
    float sz = (xp[2 * NPTS + n0 + m] - cz) * dinv;
    __syncthreads();

    {
        float v[64]; float s = 0.f, s2 = 0.f;
        #pragma unroll
        for (int i = 0; i < 64; i++) {
            int c = q * 64 + i;
            v[i] = fmaf(sx, W1s[c], fmaf(sy, W1s[CP + c], fmaf(sz, W1s[2 * CP + c], b1s[c])));
            s += v[i]; s2 += v[i] * v[i];
        }
        s  += __shfl_xor_sync(~0u, s, 1);  s  += __shfl_xor_sync(~0u, s, 2);
        s2 += __shfl_xor_sync(~0u, s2, 1); s2 += __shfl_xor_sync(~0u, s2, 2);
        float mu = s * (1.f / CP);
        float var = s2 * (1.f / CP) - mu * mu;
        float iv = rsqrtf(var + EPS);
        #pragma unroll
        for (int i = 0; i < 64; i += 2) {
            int c = q * 64 + i;
            float y0 = fmaxf((v[i] - mu) * iv * g1s[c] + be1s[c], 0.f);
            float y1 = fmaxf((v[i + 1] - mu) * iv * g1s[c + 1] + be1s[c + 1], 0.f);
            unsigned h0 = (unsigned)hbits(__float2half_rn(y0));
            unsigned h1 = (unsigned)hbits(__float2half_rn(y1));
            unsigned w = (unsigned)(c >> 1);
            unsigned idx = (unsigned)m * 128u + physA(w, (unsigned)m);
            AH[idx] = h0 | (h1 << 16);
        }
    }

    // ---- mainloop ----
    int m0w = (wid & 3) * 32, n0w = (wid >> 2) * 64;
    float acc[64];
    #pragma unroll
    for (int i = 0; i < 64; i++) acc[i] = 0.f;
    gemm_mainloop(aH_a, b_a, gW2h, gW2l, acc, t, lane, m0w, n0w);

    // ---- epilogue: +b2, LN2, col-max, fp16 -> staged smem -> g_local ----
    int wn = wid >> 2;
    #pragma unroll
    for (int mh = 0; mh < 4; mh++) {
        int mi = mh >> 1, h = mh & 1;
        int row = m0w + mi * 16 + g + 8 * h;
        float s = 0.f, s2 = 0.f;
        #pragma unroll
        for (int ni = 0; ni < 8; ni++) {
            #pragma unroll
            for (int r01 = 0; r01 < 2; r01++) {
                int c = n0w + ni * 8 + r4 * 2 + r01;
                float vv = acc[mi * 32 + ni * 4 + 2 * h + r01] + b2s[c];
                s += vv; s2 += vv * vv;
            }
        }
        s  += __shfl_xor_sync(~0u, s, 1);  s  += __shfl_xor_sync(~0u, s, 2);
        s2 += __shfl_xor_sync(~0u, s2, 1); s2 += __shfl_xor_sync(~0u, s2, 2);
        if (r4 == 0) { rr_s[row][wn] = s; rr_s2[row][wn] = s2; }
    }
    __syncthreads();
    if (t < TM) {
        float S = rr_s[t][0] + rr_s[t][1] + rr_s[t][2] + rr_s[t][3];
        float S2 = rr_s2[t][0] + rr_s2[t][1] + rr_s2[t][2] + rr_s2[t][3];
        float mu = S * (1.f / CP);
        float var = S2 * (1.f / CP) - mu * mu;
        mean_s[t] = mu; inv_s[t] = rsqrtf(var + EPS);
    }
    __syncthreads();

    float cmax[16];
    #pragma unroll
    for (int j = 0; j < 16; j++) cmax[j] = -1e30f;
    #pragma unroll
    for (int mh = 0; mh < 4; mh++) {
        int mi = mh >> 1, h = mh & 1;
        int row = m0w + mi * 16 + g + 8 * h;
        float mu = mean_s[row], iv = inv_s[row];
        #pragma unroll
        for (int ni = 0; ni < 8; ni++) {
            int c0 = n0w + ni * 8 + r4 * 2;
            float y0 = (acc[mi * 32 + ni * 4 + 2 * h] + b2s[c0] - mu) * iv * g2s[c0] + be2s[c0];
            float y1 = (acc[mi * 32 + ni * 4 + 2 * h + 1] + b2s[c0 + 1] - mu) * iv * g2s[c0 + 1] + be2s[c0 + 1];
            cmax[ni * 2]     = fmaxf(cmax[ni * 2], y0);
            cmax[ni * 2 + 1] = fmaxf(cmax[ni * 2 + 1], y1);
            unsigned h0 = (unsigned)hbits(__float2half_rn(y0));
            unsigned h1 = (unsigned)hbits(__float2half_rn(y1));
            unsigned w = (unsigned)((n0w >> 1) + ni * 4 + r4);
            unsigned idx = (unsigned)row * 128u + physA(w, (unsigned)row);
            AH[idx] = h0 | (h1 << 16);
        }
    }
    #pragma unroll
    for (int j = 0; j < 16; j++) {
        cmax[j] = fmaxf(cmax[j], __shfl_xor_sync(~0u, cmax[j], 4));
        cmax[j] = fmaxf(cmax[j], __shfl_xor_sync(~0u, cmax[j], 8));
        cmax[j] = fmaxf(cmax[j], __shfl_xor_sync(~0u, cmax[j], 16));
    }
    if (lane < 4) {
        #pragma unroll
        for (int ni = 0; ni < 8; ni++) {
            int c0 = n0w + ni * 8 + lane * 2;
            atomicMax(&g_gmaxu[bv * CP + c0], fkey(cmax[ni * 2]));
            atomicMax(&g_gmaxu[bv * CP + c0 + 1], fkey(cmax[ni * 2 + 1]));
        }
    }
    __syncthreads();
    {
        size_t gb = (size_t)blockIdx.x * 16384;
        uint4* dh = (uint4*)(g_localH + gb);
        const uint4* sh = (const uint4*)AH;
        #pragma unroll
        for (int i = 0; i < 8; i++) dh[t + i * 512] = sh[t + i * 512];
    }
}

// ---------------- stage G: gcon = b3 + global @ W3[256:512] ----------------
__global__ void stageG(const float* __restrict__ W3, const float* __restrict__ b3) {
    __shared__ float gsm[CP];
    __shared__ float part[8][32];
    int bv = blockIdx.x >> 3, seg = blockIdx.x & 7;
    int t = threadIdx.x;
    gsm[t] = fdec(g_gmaxu[bv * CP + t]);
    __syncthreads();
    int c = seg * 32 + (t & 31), jg = t >> 5;
    float a = 0.f;
    #pragma unroll 4
    for (int j = jg * 32; j < jg * 32 + 32; j++) a = fmaf(gsm[j], W3[(CP + j) * CP + c], a);
    part[jg][t & 31] = a;
    __syncthreads();
    if (t < 32) {
        float s = b3[seg * 32 + t];
        #pragma unroll
        for (int w = 0; w < 8; w++) s += part[w][t];
        g_gcon[bv * CP + seg * 32 + t] = s;
    }
}

// ---------------- stage C ----------------
__global__ __launch_bounds__(512, 1) void stageC(
    const float* __restrict__ feats, const float* __restrict__ masks,
    const float* __restrict__ g3v, const float* __restrict__ be3,
    const float* __restrict__ W4)
{
    extern __shared__ unsigned smu[];
    unsigned* AH = smu;
    __shared__ float gcs[CP], g3s[CP], be3s[CP], W4s[CP];
    __shared__ float rr_s[TM][4], rr_s2[TM][4], mean_s[TM], inv_s[TM];
    __shared__ __align__(16) float mw_s[TM];

    int t = threadIdx.x, lane = t & 31, wid = t >> 5;
    int g = lane >> 2, r4 = lane & 3;
    int bv = blockIdx.x >> 7, tile = blockIdx.x & 127;
    int b = bv >> 2, n0 = tile * TM;

    uint32_t aH_a = smem_u32(AH), b_a = smem_u32(smu + B_REGION_OFF);

    for (int i = t; i < CP; i += 512) {
        gcs[i] = g_gcon[bv * CP + i];
        g3s[i] = g3v[i]; be3s[i] = be3[i]; W4s[i] = W4[i];
    }
    {
        size_t gb = (size_t)blockIdx.x * 16384;
        const uint4* sh = (const uint4*)(g_localH + gb);
        uint4* dh = (uint4*)AH;
        #pragma unroll
        for (int i = 0; i < 8; i++) dh[t + i * 512] = sh[t + i * 512];
    }

    int m0w = (wid & 3) * 32, n0w = (wid >> 2) * 64;
    float acc[64];
    #pragma unroll
    for (int i = 0; i < 64; i++) acc[i] = 0.f;
    gemm_mainloop(aH_a, b_a, gW3h, gW3l, acc, t, lane, m0w, n0w);

    // ---- epilogue: +gcon, LN3, relu, dot W4, sigmoid -> mw ----
    int wn = wid >> 2;
    #pragma unroll
    for (int mh = 0; mh < 4; mh++) {
        int mi = mh >> 1, h = mh & 1;
        int row = m0w + mi * 16 + g + 8 * h;
        float s = 0.f, s2 = 0.f;
        #pragma unroll
        for (int ni = 0; ni < 8; ni++) {
            #pragma unroll
            for (int r01 = 0; r01 < 2; r01++) {
                int c = n0w + ni * 8 + r4 * 2 + r01;
                float vv = acc[mi * 32 + ni * 4 + 2 * h + r01] + gcs[c];
                s += vv; s2 += vv * vv;
            }
        }
        s  += __shfl_xor_sync(~0u, s, 1);  s  += __shfl_xor_sync(~0u, s, 2);
        s2 += __shfl_xor_sync(~0u, s2, 1); s2 += __shfl_xor_sync(~0u, s2, 2);
        if (r4 == 0) { rr_s[row][wn] = s; rr_s2[row][wn] = s2; }
    }
    __syncthreads();
    if (t < TM) {
        float S = rr_s[t][0] + rr_s[t][1] + rr_s[t][2] + rr_s[t][3];
        float S2 = rr_s2[t][0] + rr_s2[t][1] + rr_s2[t][2] + rr_s2[t][3];
        float mu = S * (1.f / CP);
        float var = S2 * (1.f / CP) - mu * mu;
        mean_s[t] = mu; inv_s[t] = rsqrtf(var + EPS);
    }
    __syncthreads();
    #pragma unroll
    for (int mh = 0; mh < 4; mh++) {
        int mi = mh >> 1, h = mh & 1;
        int row = m0w + mi * 16 + g + 8 * h;
        float mu = mean_s[row], iv = inv_s[row];
        float dp = 0.f;
        #pragma unroll
        for (int ni = 0; ni < 8; ni++) {
            #pragma unroll
            for (int r01 = 0; r01 < 2; r01++) {
                int c = n0w + ni * 8 + r4 * 2 + r01;
                float y = fmaxf((acc[mi * 32 + ni * 4 + 2 * h + r01] + gcs[c] - mu) * iv * g3s[c] + be3s[c], 0.f);
                dp = fmaf(y, W4s[c], dp);
            }
        }
        dp += __shfl_xor_sync(~0u, dp, 1); dp += __shfl_xor_sync(~0u, dp, 2);
        if (r4 == 0) rr_s[row][wn] = dp;
    }
    __syncthreads();
    if (t < TM) {
        float dpv = rr_s[t][0] + rr_s[t][1] + rr_s[t][2] + rr_s[t][3];
        float w = 2.f / (1.f + expf(-dpv));
        mw_s[t] = w * masks[(size_t)bv * NPTS + n0 + t];
    }
    __syncthreads();

    // ---- pooling: warp per 16 channels ----
    const float* fb = feats + (size_t)b * CP * NPTS;
    float4 m4 = ((const float4*)mw_s)[lane];
    #pragma unroll 1
    for (int ci = 0; ci < 16; ci++) {
        int c = wid * 16 + ci;
        float4 f = *(const float4*)(fb + (size_t)c * NPTS + n0 + lane * 4);
        float p = f.x * m4.x + f.y * m4.y + f.z * m4.z + f.w * m4.w;
        #pragma unroll
        for (int off = 16; off; off >>= 1) p += __shfl_xor_sync(~0u, p, off);
        if (lane == 0) g_poolpart[(size_t)blockIdx.x * CP + c] = p;
    }
    if (wid == 0) {
        float d = mw_s[lane] + mw_s[lane + 32] + mw_s[lane + 64] + mw_s[lane + 96];
        #pragma unroll
        for (int off = 16; off; off >>= 1) d += __shfl_xor_sync(~0u, d, off);
        if (lane == 0) g_denpart[blockIdx.x] = d;
    }
}

// ---------------- stage D: final reduce ----------------
__global__ void stageD(float* __restrict__ out) {
    int bv = blockIdx.x, t = threadIdx.x;
    __shared__ float dsum_s;
    float p = 0.f;
    for (int tl = 0; tl < NTILES; tl++)
        p += g_poolpart[((size_t)(bv * NTILES + tl)) * CP + t];
    if (t == 0) {
        float d = 0.f;
        for (int tl = 0; tl < NTILES; tl++) d += g_denpart[bv * NTILES + tl];
        dsum_s = fmaxf(d, 1e-8f);
    }
    __syncthreads();
    out[bv * CP + t] = p / dsum_s + fdec(g_gmaxu[bv * CP + t]);
}

extern "C" void kernel_launch(void* const* d_in, const int* in_sizes, int n_in,
                              void* d_out, int out_size) {
    const float* xyz   = (const float*)d_in[0];
    const float* feats = (const float*)d_in[1];
    const float* masks = (const float*)d_in[2];
    const float* W1  = (const float*)d_in[3];
    const float* b1  = (const float*)d_in[4];
    const float* g1  = (const float*)d_in[5];
    const float* be1 = (const float*)d_in[6];
    const float* W2  = (const float*)d_in[7];
    const float* b2  = (const float*)d_in[8];
    const float* g2  = (const float*)d_in[9];
    const float* be2 = (const float*)d_in[10];
    const float* W3  = (const float*)d_in[11];
    const float* b3  = (const float*)d_in[12];
    const float* g3  = (const float*)d_in[13];
    const float* be3 = (const float*)d_in[14];
    const float* W4  = (const float*)d_in[15];

    cudaFuncSetAttribute(stageB, cudaFuncAttributeMaxDynamicSharedMemorySize, DSMEM_BYTES);
    cudaFuncSetAttribute(stageC, cudaFuncAttributeMaxDynamicSharedMemorySize, DSMEM_BYTES);

    stageAP<<<352, 256>>>(W2, W3, xyz, masks);
    stageB<<<NBLK, 512, DSMEM_BYTES>>>(xyz, W1, b1, g1, be1, b2, g2, be2);
    stageG<<<BV * 8, 256>>>(W3, b3);
    stageC<<<NBLK, 512, DSMEM_BYTES>>>(feats, masks, g3, be3, W4);
    stageD<<<BV, CP>>>((float*)d_out);
}